// round 7
// baseline (speedup 1.0000x reference)
#include <cuda_runtime.h>
#include <math.h>

// Problem constants (fixed shapes from reference setup_inputs)
#define BN   32
#define NA   24564
#define NCLS 81
#define NO   16
#define TOTROWS (BN * NA)   // 786048

// ---------------- scratch (device globals: no allocation allowed) ----------
__device__ float              g_negconf[BN * NA];
__device__ int2               g_argm[BN * NA];     // per-anchor (biou bits, best obj)
__device__ unsigned long long g_best[BN * NO];
__device__ int                g_npos[BN];
__device__ int                g_npos_total;
__device__ int                g_done;
__device__ double             g_posconf;
__device__ double             g_sl1;
__device__ double             g_hard;

// ---------------- init --------------------------------------------------
__global__ void k_init() {
    int i = threadIdx.x;
    if (i < BN * NO) g_best[i] = 0ull;
    if (i < BN)      g_npos[i] = 0;
    if (i == 0) {
        g_npos_total = 0; g_done = 0;
        g_posconf = 0.0; g_sl1 = 0.0; g_hard = 0.0;
    }
}

// IoU in the exact op order of the reference (max/min/clip/mul/div)
__device__ __forceinline__ float iou_xy(
    float ax0, float ay0, float ax1, float ay1, float areaA,
    float dx0, float dy0, float dx1, float dy1, float areaB)
{
    float ltx = fmaxf(ax0, dx0), lty = fmaxf(ay0, dy0);
    float rbx = fminf(ax1, dx1), rby = fminf(ay1, dy1);
    float w = fmaxf(rbx - ltx, 0.0f), h = fmaxf(rby - lty, 0.0f);
    float inter = w * h;
    return inter / (areaA + areaB - inter);
}

// ---------------- fused match pass A ---------------------------------------
// ONE IoU sweep produces both reductions:
//   per-anchor argmax over 16 objects  -> g_argm   (strict > : first max)
//   per-object argmax over anchors     -> g_best   (packed key, ties -> min n)
#define MA_T 256
__global__ void __launch_bounds__(MA_T) k_matchA(const float4* __restrict__ boxes,
                                                 const float4* __restrict__ dboxes)
{
    int b = blockIdx.y;
    int n = blockIdx.x * MA_T + threadIdx.x;

    __shared__ float4 sbox[NO];
    __shared__ float  sarea[NO];
    __shared__ unsigned long long sb[NO];
    if (threadIdx.x < NO) {
        float4 bx = boxes[b * NO + threadIdx.x];
        sbox[threadIdx.x]  = bx;
        sarea[threadIdx.x] = (bx.z - bx.x) * (bx.w - bx.y);
        sb[threadIdx.x]    = 0ull;
    }
    __syncthreads();

    if (n < NA) {
        float4 d = __ldg(&dboxes[n]);
        float dx0 = d.x - d.z / 2.0f, dy0 = d.y - d.w / 2.0f;
        float dx1 = d.x + d.z / 2.0f, dy1 = d.y + d.w / 2.0f;
        float areaB = (dx1 - dx0) * (dy1 - dy0);

        float biou = -1.0f; int bo = 0;
#pragma unroll
        for (int o = 0; o < NO; o++) {
            float4 a = sbox[o];
            float v = iou_xy(a.x, a.y, a.z, a.w, sarea[o], dx0, dy0, dx1, dy1, areaB);
            if (v > biou) { biou = v; bo = o; }      // strict > : first max wins
            unsigned long long key =
                ((unsigned long long)__float_as_uint(v) << 32) |
                (unsigned long long)(0xFFFFFFFFu - (unsigned)n);
            if (key > sb[o]) atomicMax(&sb[o], key); // guarded: skip hopeless
        }
        g_argm[b * NA + n] = make_int2(__float_as_int(biou), bo);
    }
    __syncthreads();
    if (threadIdx.x < NO) {
        unsigned long long k = sb[threadIdx.x];
        if (k > g_best[b * NO + threadIdx.x])
            atomicMax(&g_best[b * NO + threadIdx.x], k);
    }
}

// ------- fused: match-B (override/label/encode) + softmax conf + loc loss --
// ILP=4: each warp handles 4 consecutive rows (NA % 4 == 0, so a warp never
// straddles a batch). Lanes 0-15 carry the 16 objects' box/label/override.
// All warp collectives are full-mask under warp-uniform control flow.
#define B_T  256
#define RPW  4

__global__ void __launch_bounds__(B_T) k_conf(const float*  __restrict__ cls,
                                              const float*  __restrict__ locs,
                                              const float4* __restrict__ boxes,
                                              const int*    __restrict__ labels,
                                              const float4* __restrict__ dboxes)
{
    const unsigned FULL = 0xffffffffu;
    int wg   = (blockIdx.x * B_T + threadIdx.x) >> 5;   // global warp id
    int lane = threadIdx.x & 31;
    int wip  = threadIdx.x >> 5;
    int row0 = wg * RPW;
    int b    = row0 / NA;          // warp-uniform
    int n0   = row0 - b * NA;

    // per-object state on lanes 0..15 (hot in L2: tiny working set per batch)
    float4   obox = make_float4(0.f, 0.f, 0.f, 0.f);
    int      olab = 0;
    unsigned osov = 0xFFFFFFFFu;
    if (lane < NO) {
        obox = __ldg(&boxes[b * NO + lane]);
        olab = __ldg(&labels[b * NO + lane]);
        unsigned long long be = g_best[b * NO + lane];
        osov = 0xFFFFFFFFu - (unsigned)(be & 0xFFFFFFFFull);
    }
    int2 am = make_int2(0, 0);
    if (lane < RPW) am = g_argm[row0 + lane];

    // -------- softmax logits (the HBM-dominant part) --------
    const float* p = cls + (size_t)row0 * NCLS;
    float v0[RPW], v1[RPW], v2[RPW];
#pragma unroll
    for (int r = 0; r < RPW; r++) {                      // 12 front-batched LDGs
        v0[r] = __ldg(p + r * NCLS + lane);
        v1[r] = __ldg(p + r * NCLS + 32 + lane);
        v2[r] = (lane < 17) ? __ldg(p + r * NCLS + 64 + lane) : 0.0f;
    }
    float s[RPW];
#pragma unroll
    for (int r = 0; r < RPW; r++)
        s[r] = __expf(v0[r]) + __expf(v1[r]) +
               ((lane < 17) ? __expf(v2[r]) : 0.0f);
#pragma unroll
    for (int o = 16; o > 0; o >>= 1) {                   // 4 interleaved chains
#pragma unroll
        for (int r = 0; r < RPW; r++)
            s[r] += __shfl_xor_sync(FULL, s[r], o);
    }

    // -------- match-B: labels in-register --------
    int   lbl[RPW];
    int   bo_[RPW];
    float nc[RPW];
#pragma unroll
    for (int r = 0; r < RPW; r++) {
        int n_r = n0 + r;
        int ax  = __shfl_sync(FULL, am.x, r);
        int ay  = __shfl_sync(FULL, am.y, r);
        unsigned bal = __ballot_sync(FULL, lane < NO && osov == (unsigned)n_r);
        int   bo;  float biou;
        if (bal) { bo = 31 - __clz(bal); biou = 1.0f; }  // highest o = last write
        else     { bo = ay; biou = __int_as_float(ax); }
        int l = (biou < 0.5f) ? 0 : __shfl_sync(FULL, olab, bo);
        lbl[r] = l; bo_[r] = bo;
    }

    // -------- conf = -log_softmax[label] (logit pulled from registers) -----
#pragma unroll
    for (int r = 0; r < RPW; r++) {
        float sel = (lbl[r] < 32) ? v0[r] : ((lbl[r] < 64) ? v1[r] : v2[r]);
        float logit = __shfl_sync(FULL, sel, lbl[r] & 31);
        float conf  = __logf(s[r]) - logit;
        nc[r] = (lbl[r] != 0) ? -conf : conf;            // positives stash -conf
    }

    // -------- positives: loc loss + pos_conf (rare path, warp-uniform) -----
    __shared__ float sp[B_T / 32], ss[B_T / 32];
    float myp = 0.0f, mys = 0.0f;
    int cnt = 0;
#pragma unroll
    for (int r = 0; r < RPW; r++) {
        if (lbl[r] != 0) {                               // warp-uniform condition
            cnt++;
            float ax0 = __shfl_sync(FULL, obox.x, bo_[r]);
            float ay0 = __shfl_sync(FULL, obox.y, bo_[r]);
            float ax1 = __shfl_sync(FULL, obox.z, bo_[r]);
            float ay1 = __shfl_sync(FULL, obox.w, bo_[r]);
            float4 d  = __ldg(&dboxes[n0 + r]);          // broadcast load
            float bcx = (ax1 + ax0) / 2.0f, bcy = (ay1 + ay0) / 2.0f;
            float bw  = ax1 - ax0,          bh  = ay1 - ay0;
            float tx = (bcx - d.x) / (d.z / 10.0f + 1e-6f);
            float ty = (bcy - d.y) / (d.w / 10.0f + 1e-6f);
            float tz = logf(bw / d.z + 1e-6f) * 5.0f;
            float tw = logf(bh / d.w + 1e-6f) * 5.0f;
            if (lane == 0) {
                myp += -nc[r];                           // recover conf
                float4 lp = __ldg((const float4*)(locs + (size_t)(row0 + r) * 4));
                float acc = 0.0f, dd;
                dd = fabsf(lp.x - tx); acc += (dd < 1.0f) ? 0.5f * dd * dd : dd - 0.5f;
                dd = fabsf(lp.y - ty); acc += (dd < 1.0f) ? 0.5f * dd * dd : dd - 0.5f;
                dd = fabsf(lp.z - tz); acc += (dd < 1.0f) ? 0.5f * dd * dd : dd - 0.5f;
                dd = fabsf(lp.w - tw); acc += (dd < 1.0f) ? 0.5f * dd * dd : dd - 0.5f;
                mys += acc;
            }
            nc[r] = 0.0f;                                // negconf = 0 for positives
        }
    }
    if (lane == 0) {
        ((float4*)g_negconf)[wg] = make_float4(nc[0], nc[1], nc[2], nc[3]);
        sp[wip] = myp; ss[wip] = mys;
        if (cnt) {                                       // per-warp, rare
            atomicAdd(&g_npos[b], cnt);
            atomicAdd(&g_npos_total, cnt);
        }
    }
    __syncthreads();
    if (threadIdx.x == 0) {
        float tp = 0.0f, ts = 0.0f;
#pragma unroll
        for (int i = 0; i < B_T / 32; i++) { tp += sp[i]; ts += ss[i]; }
        if (tp != 0.0f) atomicAdd(&g_posconf, (double)tp);
        if (ts != 0.0f) atomicAdd(&g_sl1, (double)ts);
    }
}

// ------- exact top-k sum: 4-pass MSB radix select ---------------------------
// match_any COUNT-ONLY aggregation defuses concentrated-bin conflicts. The
// histogram loop is padded to a UNIFORM trip count (6144 = 6*1024) so every
// lane reaches the warp collectives; out-of-range lanes carry pred=false.
#define C_T   1024
#define NA4   (NA / 4)            // 6141 exactly
#define NA4PAD 6144               // next multiple of C_T

__device__ __forceinline__ void hist_count(unsigned* hist, unsigned dg, bool pred)
{
    unsigned active = __ballot_sync(0xffffffffu, pred);
    if (pred) {
        unsigned peers = __match_any_sync(active, dg);   // all peers same dg
        int leader = __ffs(peers) - 1;
        if ((int)(threadIdx.x & 31) == leader)
            atomicAdd(&hist[dg], (unsigned)__popc(peers));
    }
}

__global__ void __launch_bounds__(C_T) k_topk(float* __restrict__ out)
{
    int b = blockIdx.x;
    int tid = threadIdx.x;
    __shared__ unsigned hist[256];
    __shared__ int s_digit, s_rem;
    __shared__ double swsum[C_T / 32];
    __shared__ int    swcnt[C_T / 32];
    __shared__ int    s_last;

    int k = 3 * g_npos[b];
    if (k > NA) k = NA;

    if (k > 0) {
        const float4* v4 = (const float4*)&g_negconf[b * NA];
        unsigned prefix = 0, pmask = 0;
        int rem = k;
#pragma unroll
        for (int p = 3; p >= 0; --p) {
            if (tid < 256) hist[tid] = 0;
            __syncthreads();
            int sh = p * 8;
            for (int j = tid; j < NA4PAD; j += C_T) {    // UNIFORM trip count
                bool inb = (j < NA4);
                float4 x = inb ? __ldg(&v4[j]) : make_float4(0.f, 0.f, 0.f, 0.f);
                float vv[4] = {x.x, x.y, x.z, x.w};
#pragma unroll
                for (int c = 0; c < 4; c++) {
                    unsigned bits = __float_as_uint(vv[c]);
                    hist_count(hist, (bits >> sh) & 255u,
                               inb && ((bits & pmask) == prefix));
                }
            }
            __syncthreads();
            if (tid == 0) {
                int r = rem, d = 255;
                for (; d > 0; --d) { int c = (int)hist[d]; if (r <= c) break; r -= c; }
                s_digit = d; s_rem = r;
            }
            __syncthreads();
            prefix |= ((unsigned)s_digit) << sh;
            pmask  |= 0xFFu << sh;
            rem = s_rem;
            __syncthreads();
        }
        // prefix == bits of the k-th largest value t. Sum all strictly greater.
        double sg = 0.0; int cg = 0;
        for (int j = tid; j < NA4; j += C_T) {           // no collectives: ragged ok
            float4 x = __ldg(&v4[j]);
            if (__float_as_uint(x.x) > prefix) { sg += (double)x.x; cg++; }
            if (__float_as_uint(x.y) > prefix) { sg += (double)x.y; cg++; }
            if (__float_as_uint(x.z) > prefix) { sg += (double)x.z; cg++; }
            if (__float_as_uint(x.w) > prefix) { sg += (double)x.w; cg++; }
        }
#pragma unroll
        for (int o = 16; o > 0; o >>= 1) {               // uniform: all lanes here
            sg += __shfl_xor_sync(0xffffffffu, sg, o);
            cg += __shfl_xor_sync(0xffffffffu, cg, o);
        }
        if ((tid & 31) == 0) { swsum[tid >> 5] = sg; swcnt[tid >> 5] = cg; }
        __syncthreads();
        if (tid < 32) {
            double s2 = (tid < C_T / 32) ? swsum[tid] : 0.0;
            int    c2 = (tid < C_T / 32) ? swcnt[tid] : 0;
#pragma unroll
            for (int o = 16; o > 0; o >>= 1) {
                s2 += __shfl_xor_sync(0xffffffffu, s2, o);
                c2 += __shfl_xor_sync(0xffffffffu, c2, o);
            }
            if (tid == 0) {
                double t = (double)__uint_as_float(prefix);
                atomicAdd(&g_hard, s2 + (double)(k - c2) * t);  // exact ties
            }
        }
    }

    // completion ticket: last block finalizes the scalar loss
    __threadfence();
    if (tid == 0) {
        int t = atomicAdd(&g_done, 1);
        s_last = (t == BN - 1);
    }
    __syncthreads();
    if (tid == 0 && s_last) {
        double npt  = (double)(*(volatile int*)&g_npos_total);
        double sl1  = *(volatile double*)&g_sl1;
        double pc   = *(volatile double*)&g_posconf;
        double hd   = *(volatile double*)&g_hard;
        double loc  = sl1 / (npt * 4.0);
        double conf = (hd + pc) / npt;
        out[0] = (float)(0.5 * loc + conf);
    }
}

// ---------------- launcher --------------------------------------------------
extern "C" void kernel_launch(void* const* d_in, const int* in_sizes, int n_in,
                              void* d_out, int out_size)
{
    (void)in_sizes; (void)n_in; (void)out_size;
    const float*  locs   = (const float*)d_in[0];
    const float*  cls    = (const float*)d_in[1];
    const float4* boxes  = (const float4*)d_in[2];
    const int*    labels = (const int*)d_in[3];
    const float4* dboxes = (const float4*)d_in[4];

    k_init<<<1, 512>>>();
    dim3 gm((NA + MA_T - 1) / MA_T, BN);
    k_matchA<<<gm, MA_T>>>(boxes, dboxes);
    int blocksB = TOTROWS / (RPW * (B_T / 32));   // 24564, exact
    k_conf<<<blocksB, B_T>>>(cls, locs, boxes, labels, dboxes);
    k_topk<<<BN, C_T>>>((float*)d_out);
}